// round 9
// baseline (speedup 1.0000x reference)
#include <cuda_runtime.h>

#define N_NODES 8192
#define C_DIM   16
#define NC_ITEMS (N_NODES * C_DIM)
#define R_ANCH  32
#define XD      224
#define NCHUNK  64
#define ESCALE  0.15811388300841898f

typedef unsigned long long ull;

__device__ float g_logits[NC_ITEMS * R_ANCH];
__device__ float g_pm[C_DIM * 16 * R_ANCH];
__device__ float g_ps[C_DIM * 16 * R_ANCH];
__device__ float g_part[NCHUNK * C_DIM * R_ANCH * XD];
__device__ float g_gbuf[R_ANCH * C_DIM * XD];
__device__ float g_ke[C_DIM * R_ANCH * XD];
__device__ float g_ve[C_DIM * R_ANCH * XD];
__device__ float g_q[(size_t)NC_ITEMS * XD];
__device__ float g_wqT[160 * 128];
__device__ float g_wpT[160 * 32];
__device__ float g_wsvT[128 * 32];

__device__ __forceinline__ float sigf(float x) { return 1.0f / (1.0f + __expf(-x)); }
#define FMA2(d, a, b) asm("fma.rn.f32x2 %0, %1, %2, %0;" : "+l"(d) : "l"(a), "l"(b))
__device__ __forceinline__ ull packx2(float x) {
    ull o; unsigned r = __float_as_uint(x);
    asm("mov.b64 %0, {%1, %1};" : "=l"(o) : "r"(r));
    return o;
}
__device__ __forceinline__ ull pack2(float a, float b) {
    ull o;
    asm("mov.b64 %0, {%1, %2};" : "=l"(o) : "f"(a), "f"(b));
    return o;
}
__device__ __forceinline__ float2 unpk(ull u) {
    float2 f;
    asm("mov.b64 {%0, %1}, %2;" : "=f"(f.x), "=f"(f.y) : "l"(u));
    return f;
}

// ---- k0a/b/c: weight transposes (3 launches so ka is 4th = profiled) ----
__global__ void k0a(const float* __restrict__ qw) {
    int i = blockIdx.x * 256 + threadIdx.x;
    if (i < 160 * 128) { int k = i >> 7, o = i & 127; g_wqT[i] = qw[o * 160 + k]; }
}
__global__ void k0b(const float* __restrict__ pw) {
    int i = blockIdx.x * 256 + threadIdx.x;
    if (i < 160 * 32) { int k = i >> 5, a = i & 31; g_wpT[i] = pw[a * 160 + k]; }
}
__global__ void k0c(const float* __restrict__ sv) {
    int i = blockIdx.x * 256 + threadIdx.x;
    if (i < 128 * 32) { int k = i >> 5, m = i & 31; g_wsvT[i] = sv[m * 128 + k]; }
}

// ============================================================
// KA: 32 items/block, 512 threads, 2 blocks/SM.
// Main phase: warps 0-7 s_out (16i x 32o tiles), 8-11 logits, 12-15 v_out.
// Big weights streamed from global (__ldg); only tiny ones in smem.
// ============================================================
__global__ void __launch_bounds__(512, 2) ka_gvp(
    const float* __restrict__ s, const float* __restrict__ v,
    const float* __restrict__ q_wh, const float* __restrict__ q_ws_b,
    const float* __restrict__ q_wv, const float* __restrict__ q_wsv_b,
    const float* __restrict__ wp_wh, const float* __restrict__ wp_ws_b)
{
    extern __shared__ float sm[];
    float* whq  = sm;            // [32][34]
    float* whp  = sm + 1088;     // [32][34]
    float* wvvT = sm + 2176;     // [32][32] h-major
    float* sbq  = sm + 3200;     // 128
    float* sbp  = sm + 3328;     // 32
    float* svb  = sm + 3360;     // 32
    float* xs   = sm + 3392;     // [160][36] rows 0..127 x_s/sig, 128..159 vn_q
    float* vnp  = sm + 9152;     // [32][36]
    float* vhs  = sm + 10304;    // [32][97]
    float* gsb  = sm + 13408;    // [32][33]
    float* vbuf = sm + 14464;    // [16][104]  -> total 16128 floats (64.5 KB)

    int tid = threadIdx.x, warp = tid >> 5, lane = tid & 31;
    int base = blockIdx.x * 32;

    for (int i = tid; i < 1024; i += 512) {
        int r = i >> 5, cc = i & 31;
        whq[r * 34 + cc] = q_wh[i];
        whp[r * 34 + cc] = wp_wh[i];
        wvvT[i] = q_wv[cc * 32 + r];    // wvvT[h][m] = wv[m][h]
    }
    if (tid < 128) sbq[tid] = q_ws_b[tid];
    if (tid < 32)  { sbp[tid] = wp_ws_b[tid]; svb[tid] = q_wsv_b[tid]; }
    __syncthreads();

    // ---- stage A: 16 warps x 2 items
    {
        float* vb = vbuf + warp * 104;
        for (int ii = 0; ii < 2; ii++) {
            int i = warp * 2 + ii;
            size_t git = (size_t)(base + i);
            const float* sp = s + git * 128;
            const float* vp = v + git * 96;
            #pragma unroll
            for (int k = 0; k < 4; k++) xs[(lane + 32 * k) * 36 + i] = sp[lane + 32 * k];
            #pragma unroll
            for (int k = 0; k < 3; k++) {
                int pos = lane + 32 * k;
                float val = vp[pos];
                int m = pos / 3, d = pos - m * 3;
                vb[d * 34 + m] = val;
            }
            __syncwarp();
            ull aq0 = 0, aq1 = 0, aq2 = 0, ap0 = 0, ap1 = 0, ap2 = 0;
            #pragma unroll
            for (int m2 = 0; m2 < 32; m2 += 2) {
                ull wqp = *(const ull*)&whq[lane * 34 + m2];
                ull wpp = *(const ull*)&whp[lane * 34 + m2];
                ull v0 = *(const ull*)&vb[m2];
                ull v1 = *(const ull*)&vb[34 + m2];
                ull v2 = *(const ull*)&vb[68 + m2];
                FMA2(aq0, v0, wqp); FMA2(aq1, v1, wqp); FMA2(aq2, v2, wqp);
                FMA2(ap0, v0, wpp); FMA2(ap1, v1, wpp); FMA2(ap2, v2, wpp);
            }
            float2 f;
            f = unpk(aq0); float a0 = f.x + f.y;
            f = unpk(aq1); float a1 = f.x + f.y;
            f = unpk(aq2); float a2 = f.x + f.y;
            f = unpk(ap0); float b0 = f.x + f.y;
            f = unpk(ap1); float b1 = f.x + f.y;
            f = unpk(ap2); float b2 = f.x + f.y;
            vhs[i * 97 + lane] = a0; vhs[i * 97 + 32 + lane] = a1; vhs[i * 97 + 64 + lane] = a2;
            xs[(128 + lane) * 36 + i] = sqrtf(fmaxf(a0 * a0 + a1 * a1 + a2 * a2, 1e-8f));
            vnp[lane * 36 + i]        = sqrtf(fmaxf(b0 * b0 + b1 * b1 + b2 * b2, 1e-8f));
            __syncwarp();
        }
    }
    __syncthreads();

    ull acc[2][4] = {};   // s_out accs / later sig pairs
    ull vo[3][4]  = {};   // v_out accs

    if (warp < 8) {
        // ---- s_out: warp tile 16i x 32o; thread 4i x 4o; weights via LDG
        int itile = (warp & 1) * 16, otile = (warp >> 1) * 32;
        int r = lane >> 3, cc = lane & 7;
        const float* xb = xs + itile + r * 4;
        const float4* wb = (const float4*)(g_wqT + otile + cc * 4);
        #pragma unroll 4
        for (int k = 0; k < 160; k++) {
            longlong2 xv = *(const longlong2*)(xb + k * 36);
            float4 wf = __ldg(wb + k * 32);
            ull w0 = packx2(wf.x), w1 = packx2(wf.y), w2 = packx2(wf.z), w3 = packx2(wf.w);
            FMA2(acc[0][0], (ull)xv.x, w0); FMA2(acc[0][1], (ull)xv.x, w1);
            FMA2(acc[0][2], (ull)xv.x, w2); FMA2(acc[0][3], (ull)xv.x, w3);
            FMA2(acc[1][0], (ull)xv.y, w0); FMA2(acc[1][1], (ull)xv.y, w1);
            FMA2(acc[1][2], (ull)xv.y, w2); FMA2(acc[1][3], (ull)xv.y, w3);
        }
        float bb[4];
        #pragma unroll
        for (int u = 0; u < 4; u++) bb[u] = sbq[otile + cc * 4 + u];
        int head = otile >> 5;
        #pragma unroll
        for (int p = 0; p < 2; p++) {
            int i0 = itile + r * 4 + 2 * p;
            float s0[4], s1[4];
            #pragma unroll
            for (int u = 0; u < 4; u++) {
                float2 fr = unpk(acc[p][u]);
                float soa = fr.x + bb[u], sob = fr.y + bb[u];
                float ga = sigf(soa), gb = sigf(sob);
                s0[u] = soa * ga; s1[u] = sob * gb;
                acc[p][u] = pack2(ga, gb);
            }
            *(float4*)&g_q[(size_t)(base + i0) * 224 + head * 56 + cc * 4] =
                make_float4(s0[0], s0[1], s0[2], s0[3]);
            *(float4*)&g_q[(size_t)(base + i0 + 1) * 224 + head * 56 + cc * 4] =
                make_float4(s1[0], s1[1], s1[2], s1[3]);
        }
    } else if (warp < 12) {
        // ---- logits: 4 warps; thread = 1 item x 8 outs; weights via LDG
        int i = lane, jg = warp - 8;
        ull la[4] = {};
        const float* wrow = g_wpT + jg * 8;
        #pragma unroll 2
        for (int k = 0; k < 128; k++) {
            ull xp = packx2(xs[k * 36 + i]);
            double2 wa = __ldg((const double2*)(wrow + k * 32));
            double2 wb2 = __ldg((const double2*)(wrow + k * 32 + 4));
            FMA2(la[0], xp, __double_as_longlong(wa.x));
            FMA2(la[1], xp, __double_as_longlong(wa.y));
            FMA2(la[2], xp, __double_as_longlong(wb2.x));
            FMA2(la[3], xp, __double_as_longlong(wb2.y));
        }
        #pragma unroll 2
        for (int k = 0; k < 32; k++) {
            ull xp = packx2(vnp[k * 36 + i]);
            double2 wa = __ldg((const double2*)(wrow + (128 + k) * 32));
            double2 wb2 = __ldg((const double2*)(wrow + (128 + k) * 32 + 4));
            FMA2(la[0], xp, __double_as_longlong(wa.x));
            FMA2(la[1], xp, __double_as_longlong(wa.y));
            FMA2(la[2], xp, __double_as_longlong(wb2.x));
            FMA2(la[3], xp, __double_as_longlong(wb2.y));
        }
        float2 f0 = unpk(la[0]), f1 = unpk(la[1]), f2 = unpk(la[2]), f3 = unpk(la[3]);
        const float* bp = sbp + jg * 8;
        size_t gl = (size_t)(base + i) * 32 + jg * 8;
        *(float4*)&g_logits[gl]     = make_float4(f0.x + bp[0], f0.y + bp[1], f1.x + bp[2], f1.y + bp[3]);
        *(float4*)&g_logits[gl + 4] = make_float4(f2.x + bp[4], f2.y + bp[5], f3.x + bp[6], f3.y + bp[7]);
    } else {
        // ---- v_out accumulate: 4 warps; thread = 1 item x 8 m x 3 d
        int i = lane, mg = warp - 12;
        const float* wvb = wvvT + mg * 8;
        const float* vr = vhs + i * 97;
        #pragma unroll 2
        for (int h = 0; h < 32; h++) {
            ull v0 = packx2(vr[h]);
            ull v1 = packx2(vr[32 + h]);
            ull v2 = packx2(vr[64 + h]);
            double2 wa = *(const double2*)(wvb + h * 32);
            double2 wb2 = *(const double2*)(wvb + h * 32 + 4);
            ull w0 = __double_as_longlong(wa.x), w1 = __double_as_longlong(wa.y);
            ull w2 = __double_as_longlong(wb2.x), w3 = __double_as_longlong(wb2.y);
            FMA2(vo[0][0], v0, w0); FMA2(vo[0][1], v0, w1); FMA2(vo[0][2], v0, w2); FMA2(vo[0][3], v0, w3);
            FMA2(vo[1][0], v1, w0); FMA2(vo[1][1], v1, w1); FMA2(vo[1][2], v1, w2); FMA2(vo[1][3], v1, w3);
            FMA2(vo[2][0], v2, w0); FMA2(vo[2][1], v2, w1); FMA2(vo[2][2], v2, w2); FMA2(vo[2][3], v2, w3);
        }
    }
    __syncthreads();   // all xs/vnp/vhs readers done

    if (warp < 8) {
        // sig pairs -> xs rows 0..127
        int itile = (warp & 1) * 16, otile = (warp >> 1) * 32;
        int r = lane >> 3, cc = lane & 7;
        #pragma unroll
        for (int p = 0; p < 2; p++) {
            int i0 = itile + r * 4 + 2 * p;
            #pragma unroll
            for (int u = 0; u < 4; u++) {
                float2 fr = unpk(acc[p][u]);
                int o = otile + cc * 4 + u;
                xs[o * 36 + i0]     = fr.x;
                xs[o * 36 + i0 + 1] = fr.y;
            }
        }
    }
    __syncthreads();   // sig visible

    if (warp < 2) {
        // ---- gate: warp tile 16i x 32m; thread 4i x 4m; wsv via LDG
        int itile = warp * 16;
        int r = lane & 3, cc = lane >> 2;
        int i0 = itile + r * 4, m0 = cc * 4;
        ull ga[2][4] = {};
        const float* xb = xs + i0;
        const float4* wb = (const float4*)(g_wsvT + m0);
        #pragma unroll 4
        for (int o = 0; o < 128; o++) {
            longlong2 xv = *(const longlong2*)(xb + o * 36);
            float4 wf = __ldg(wb + o * 8);
            ull w0 = packx2(wf.x), w1 = packx2(wf.y), w2 = packx2(wf.z), w3 = packx2(wf.w);
            FMA2(ga[0][0], (ull)xv.x, w0); FMA2(ga[0][1], (ull)xv.x, w1);
            FMA2(ga[0][2], (ull)xv.x, w2); FMA2(ga[0][3], (ull)xv.x, w3);
            FMA2(ga[1][0], (ull)xv.y, w0); FMA2(ga[1][1], (ull)xv.y, w1);
            FMA2(ga[1][2], (ull)xv.y, w2); FMA2(ga[1][3], (ull)xv.y, w3);
        }
        #pragma unroll
        for (int p = 0; p < 2; p++) {
            #pragma unroll
            for (int u = 0; u < 4; u++) {
                float2 fr = unpk(ga[p][u]);
                float b = svb[m0 + u];
                gsb[(i0 + 2 * p) * 33 + m0 + u]     = sigf(fr.x + b);
                gsb[(i0 + 2 * p + 1) * 33 + m0 + u] = sigf(fr.y + b);
            }
        }
    }
    __syncthreads();   // gsb visible

    if (warp >= 12) {
        int i = lane, mg = warp - 12;
        #pragma unroll
        for (int mp = 0; mp < 4; mp++) {
            int m0 = mg * 8 + 2 * mp;
            float g0 = gsb[i * 33 + m0], g1 = gsb[i * 33 + m0 + 1];
            #pragma unroll
            for (int d = 0; d < 3; d++) {
                float2 fr = unpk(vo[d][mp]);
                vhs[i * 97 + m0 * 3 + d]       = fr.x * g0;
                vhs[i * 97 + (m0 + 1) * 3 + d] = fr.y * g1;
            }
        }
        asm volatile("bar.sync 1, 128;" ::: "memory");
        int wi = warp - 12;
        for (int ii = 0; ii < 8; ii++) {
            int item = wi * 8 + ii;
            size_t gb2 = (size_t)(base + item) * 224;
            #pragma unroll
            for (int q = 0; q < 3; q++) {
                int l = lane + 32 * q;
                int m = l / 3, d = l - m * 3;
                int gpos = (m >> 3) * 56 + 32 + (m & 7) * 3 + d;
                g_q[gb2 + gpos] = vhs[item * 97 + l];
            }
        }
    }
}

// ---- K2a: per-(c,seg) partial online softmax stats ----
__global__ void __launch_bounds__(256) k2a_stats() {
    __shared__ float redm[8 * 33], reds[8 * 33];
    int seg = blockIdx.x, c = blockIdx.y;
    int t = threadIdx.x, a = t & 31, part = t >> 5;
    float m = -3.4e38f, sum = 0.f;
    int nb = seg * 512 + part * 64;
    for (int i = 0; i < 64; i++) {
        float val = g_logits[((size_t)(nb + i) * C_DIM + c) * 32 + a];
        float nm = fmaxf(m, val);
        sum = sum * __expf(m - nm) + __expf(val - nm);
        m = nm;
    }
    redm[part * 33 + a] = m; reds[part * 33 + a] = sum;
    __syncthreads();
    if (t < 32) {
        float mm = redm[t], ss = reds[t];
        #pragma unroll
        for (int p = 1; p < 8; p++) {
            float m2 = redm[p * 33 + t], s2 = reds[p * 33 + t];
            float nm = fmaxf(mm, m2);
            ss = ss * __expf(mm - nm) + s2 * __expf(m2 - nm);
            mm = nm;
        }
        g_pm[(c * 16 + seg) * 32 + t] = mm;
        g_ps[(c * 16 + seg) * 32 + t] = ss;
    }
}

// ---- K3: compress partials (merges softmax stats inline) ----
__global__ void __launch_bounds__(224) k3_compress(const float* __restrict__ s,
                                                   const float* __restrict__ v) {
    __shared__ float xt[32 * 226];
    __shared__ float wt[32 * 33];
    __shared__ float mloc[32], iloc[32];
    int t = threadIdx.x;
    int chunk = blockIdx.x, c = blockIdx.y;
    if (t < 32) {
        float m = -3.4e38f;
        #pragma unroll
        for (int sg = 0; sg < 16; sg++) m = fmaxf(m, g_pm[(c * 16 + sg) * 32 + t]);
        float sum = 0.f;
        #pragma unroll
        for (int sg = 0; sg < 16; sg++)
            sum += g_ps[(c * 16 + sg) * 32 + t] * __expf(g_pm[(c * 16 + sg) * 32 + t] - m);
        mloc[t] = m; iloc[t] = 1.0f / sum;
    }
    int a0 = (t & 7) * 4, j0 = (t >> 3) * 8;
    ull acc[4][4] = {};
    for (int sub = 0; sub < 4; sub++) {
        __syncthreads();
        #pragma unroll 4
        for (int n = 0; n < 32; n++) {
            int item = (chunk * 128 + sub * 32 + n) * C_DIM + c;
            xt[n * 226 + t] = (t < 128) ? s[(size_t)item * 128 + t]
                                        : v[(size_t)item * 96 + (t - 128)];
        }
        for (int idx = t; idx < 1024; idx += 224) {
            int n = idx >> 5, a = idx & 31;
            int item = (chunk * 128 + sub * 32 + n) * C_DIM + c;
            wt[n * 33 + a] = __expf(g_logits[(size_t)item * 32 + a] - mloc[a]) * iloc[a];
        }
        __syncthreads();
        #pragma unroll 4
        for (int n = 0; n < 32; n++) {
            ull wpk[4];
            #pragma unroll
            for (int u = 0; u < 4; u++) wpk[u] = packx2(wt[n * 33 + a0 + u]);
            const ull* x2 = (const ull*)(xt + n * 226 + j0);
            #pragma unroll
            for (int vv = 0; vv < 4; vv++) {
                ull xp = x2[vv];
                FMA2(acc[0][vv], wpk[0], xp);
                FMA2(acc[1][vv], wpk[1], xp);
                FMA2(acc[2][vv], wpk[2], xp);
                FMA2(acc[3][vv], wpk[3], xp);
            }
        }
    }
    #pragma unroll
    for (int u = 0; u < 4; u++) {
        size_t basep = ((size_t)(chunk * C_DIM + c) * 32 + a0 + u) * 224 + j0;
        #pragma unroll
        for (int vv = 0; vv < 4; vv++) {
            float2 fr = unpk(acc[u][vv]);
            *(float2*)&g_part[basep + 2 * vv] = fr;
        }
    }
}

// ---- K4 ----
__global__ void k4_reduce() {
    int bx = blockIdx.x; int c = bx >> 5, a = bx & 31; int t = threadIdx.x;
    float sum = 0.f;
    for (int ch = 0; ch < NCHUNK; ++ch)
        sum += g_part[((size_t)(ch * C_DIM + c) * 32 + a) * 224 + t];
    g_gbuf[(a * C_DIM + c) * 224 + t] = sum;
}

// ---- K5 ----
__global__ void k5_globals(
    const float* __restrict__ k_wh, const float* __restrict__ k_ws_w, const float* __restrict__ k_ws_b,
    const float* __restrict__ k_wv, const float* __restrict__ k_wsv_w, const float* __restrict__ k_wsv_b,
    const float* __restrict__ p_wh, const float* __restrict__ p_ws_w, const float* __restrict__ p_ws_b,
    const float* __restrict__ p_wv, const float* __restrict__ p_wsv_w, const float* __restrict__ p_wsv_b) {
    __shared__ float wx[8][608];
    int tid = threadIdx.x, warp = tid >> 5, lane = tid & 31;
    int w = blockIdx.x * 8 + warp;
    int which = w >> 9, item = w & 511;
    const float* wh   = which ? p_wh    : k_wh;
    const float* wsw  = which ? p_ws_w  : k_ws_w;
    const float* wsb  = which ? p_ws_b  : k_ws_b;
    const float* wv   = which ? p_wv    : k_wv;
    const float* wsvw = which ? p_wsv_w : k_wsv_w;
    const float* wsvb = which ? p_wsv_b : k_wsv_b;
    float* x = wx[warp]; float* vhsl = x + 224; float* vns = x + 320; float* sig = x + 480;
    const float* gp = &g_gbuf[item * 224];
    #pragma unroll
    for (int k = 0; k < 7; k++) x[lane + 32 * k] = gp[lane + 32 * k];
    __syncwarp();
    float a0 = 0.f, a1 = 0.f, a2 = 0.f;
    #pragma unroll
    for (int i = 0; i < 32; i++) {
        float ww = __ldg(&wh[lane * 32 + i]);
        a0 = fmaf(x[128 + i * 3 + 0], ww, a0);
        a1 = fmaf(x[128 + i * 3 + 1], ww, a1);
        a2 = fmaf(x[128 + i * 3 + 2], ww, a2);
    }
    vhsl[lane] = a0; vhsl[32 + lane] = a1; vhsl[64 + lane] = a2;
    vns[lane] = sqrtf(fmaxf(a0 * a0 + a1 * a1 + a2 * a2, 1e-8f));
    __syncwarp();
    float so[4];
    #pragma unroll
    for (int k = 0; k < 4; k++) {
        int o = lane + 32 * k;
        float acc = __ldg(&wsb[o]);
        const float* wr = &wsw[o * 160];
        #pragma unroll
        for (int j = 0; j < 128; j++) acc = fmaf(x[j], __ldg(&wr[j]), acc);
        #pragma unroll
        for (int j = 0; j < 32; j++) acc = fmaf(vns[j], __ldg(&wr[128 + j]), acc);
        so[k] = acc;
        sig[o] = sigf(acc);
    }
    __syncwarp();
    float g = __ldg(&wsvb[lane]);
    #pragma unroll
    for (int j = 0; j < 128; j++) g = fmaf(sig[j], __ldg(&wsvw[lane * 128 + j]), g);
    float gs = sigf(g);
    float* outp = which ? g_ve : g_ke;
    int a = item >> 4, cc = item & 15;
    size_t ob = ((size_t)cc * 32 + a) * 224;
    int h = lane >> 3;
    int vpos = h * 56 + 32 + (lane & 7) * 3;
    #pragma unroll
    for (int d = 0; d < 3; d++) {
        float vo = 0.f;
        #pragma unroll
        for (int hh = 0; hh < 32; hh++) vo = fmaf(vhsl[d * 32 + hh], __ldg(&wv[lane * 32 + hh]), vo);
        outp[ob + vpos + d] = vo * gs;
    }
    #pragma unroll
    for (int k = 0; k < 4; k++) { int o = lane + 32 * k; outp[ob + k * 56 + lane] = so[k] * sig[o]; }
}

// ---- KB: attention, 32 items x 1 channel, 256 threads ----
__global__ void __launch_bounds__(256) kb_attn(float* __restrict__ out) {
    extern __shared__ float sm[];
    float* qe  = sm;            // [224][33]
    float* keT = sm + 7392;     // [224][34]
    float* ve  = sm + 15008;    // [32][226]
    float* al  = sm + 22240;    // [32][133]
    int tid = threadIdx.x;
    int c = blockIdx.y;
    int nb = blockIdx.x * 32;

    for (int idx = tid; idx < 32 * 224; idx += 256) {
        int i = idx / 224, pos = idx - i * 224;
        size_t git = (size_t)(nb + i) * 16 + c;
        qe[pos * 33 + i] = g_q[git * 224 + pos];
    }
    for (int idx = tid; idx < 32 * 224; idx += 256) {
        int r = idx / 224, pos = idx - r * 224;
        size_t gb = ((size_t)c * 32 + r) * 224 + pos;
        keT[pos * 34 + r] = g_ke[gb];
        ve[r * 226 + pos] = g_ve[gb];
    }
    __syncthreads();

    int h = tid >> 6, rem = tid & 63;

    {
        int ig = rem >> 3, rg = rem & 7;
        ull acc[4][2] = {};
        #pragma unroll 2
        for (int k = 0; k < 56; k++) {
            int row = h * 56 + k;
            ull qp[4];
            #pragma unroll
            for (int e = 0; e < 4; e++) qp[e] = packx2(qe[row * 33 + ig * 4 + e]);
            const ull* k2 = (const ull*)(keT + row * 34 + rg * 4);
            #pragma unroll
            for (int u = 0; u < 2; u++) {
                ull kp = k2[u];
                FMA2(acc[0][u], qp[0], kp);
                FMA2(acc[1][u], qp[1], kp);
                FMA2(acc[2][u], qp[2], kp);
                FMA2(acc[3][u], qp[3], kp);
            }
        }
        #pragma unroll
        for (int e = 0; e < 4; e++)
            #pragma unroll
            for (int u = 0; u < 2; u++) {
                float2 fr = unpk(acc[e][u]);
                al[(ig * 4 + e) * 133 + h * 33 + rg * 4 + 2 * u]     = fr.x * ESCALE;
                al[(ig * 4 + e) * 133 + h * 33 + rg * 4 + 2 * u + 1] = fr.y * ESCALE;
            }
    }
    __syncthreads();

    if (tid < 128) {
        int i = tid >> 2, h2 = tid & 3;
        float* row = &al[i * 133 + h2 * 33];
        float ev[32], mx = -3.4e38f;
        #pragma unroll
        for (int k = 0; k < 32; k++) { ev[k] = row[k]; mx = fmaxf(mx, ev[k]); }
        float sum = 0.f;
        #pragma unroll
        for (int k = 0; k < 32; k++) { ev[k] = __expf(ev[k] - mx); sum += ev[k]; }
        float inv = 1.0f / sum;
        #pragma unroll
        for (int k = 0; k < 32; k++) row[k] = ev[k] * inv;
    }
    __syncthreads();

    {
        int ig = rem >> 2, j = rem & 3;
        ull accs[2][4] = {};
        ull accv[2][3] = {};
        #pragma unroll 2
        for (int r = 0; r < 32; r++) {
            ull ap[2];
            #pragma unroll
            for (int e = 0; e < 2; e++) ap[e] = packx2(al[(ig * 2 + e) * 133 + h * 33 + r]);
            const ull* vs2 = (const ull*)(ve + r * 226 + h * 56 + j * 8);
            const ull* vv2 = (const ull*)(ve + r * 226 + h * 56 + 32 + j * 6);
            #pragma unroll
            for (int u = 0; u < 4; u++) {
                ull vp = vs2[u];
                FMA2(accs[0][u], ap[0], vp);
                FMA2(accs[1][u], ap[1], vp);
            }
            #pragma unroll
            for (int u = 0; u < 3; u++) {
                ull vp = vv2[u];
                FMA2(accv[0][u], ap[0], vp);
                FMA2(accv[1][u], ap[1], vp);
            }
        }
        #pragma unroll
        for (int e = 0; e < 2; e++) {
            size_t git = (size_t)(nb + ig * 2 + e) * 16 + c;
            float* ds = &out[git * 128 + h * 32 + j * 8];
            #pragma unroll
            for (int u = 0; u < 4; u++) *(float2*)&ds[2 * u] = unpk(accs[e][u]);
            float* dv = &out[(size_t)NC_ITEMS * 128 + git * 96 + h * 24 + j * 6];
            #pragma unroll
            for (int u = 0; u < 3; u++) *(float2*)&dv[2 * u] = unpk(accv[e][u]);
        }
    }
}

// ============================================================
extern "C" void kernel_launch(void* const* d_in, const int* in_sizes, int n_in,
                              void* d_out, int out_size) {
    (void)in_sizes; (void)n_in; (void)out_size;
    const float* s       = (const float*)d_in[0];
    const float* v       = (const float*)d_in[1];
    const float* wp_wh   = (const float*)d_in[2];
    const float* wp_ws_w = (const float*)d_in[3];
    const float* wp_ws_b = (const float*)d_in[4];
    const float* q_wh    = (const float*)d_in[5];
    const float* q_ws_w  = (const float*)d_in[6];
    const float* q_ws_b  = (const float*)d_in[7];
    const float* q_wv    = (const float*)d_in[8];
    const float* q_wsv_w = (const float*)d_in[9];
    const float* q_wsv_b = (const float*)d_in[10];
    const float* k_wh    = (const float*)d_in[11];
    const float* k_ws_w  = (const float*)d_in[12];
    const float* k_ws_b  = (const float*)d_in[13];
    const float* k_wv    = (const float*)d_in[14];
    const float* k_wsv_w = (const float*)d_in[15];
    const float* k_wsv_b = (const float*)d_in[16];
    const float* vp_wh   = (const float*)d_in[17];
    const float* vp_ws_w = (const float*)d_in[18];
    const float* vp_ws_b = (const float*)d_in[19];
    const float* vp_wv   = (const float*)d_in[20];
    const float* vp_wsv_w= (const float*)d_in[21];
    const float* vp_wsv_b= (const float*)d_in[22];
    float* out = (float*)d_out;

    cudaFuncSetAttribute((const void*)ka_gvp,  cudaFuncAttributeMaxDynamicSharedMemorySize, 16128 * 4);
    cudaFuncSetAttribute((const void*)kb_attn, cudaFuncAttributeMaxDynamicSharedMemorySize, 26496 * 4);

    k0a<<<80, 256>>>(q_ws_w);
    k0b<<<20, 256>>>(wp_ws_w);
    k0c<<<16, 256>>>(q_wsv_w);
    ka_gvp<<<4096, 512, 16128 * 4>>>(s, v, q_wh, q_ws_b, q_wv, q_wsv_b, wp_wh, wp_ws_b);  // 4th -> profiled
    k2a_stats<<<dim3(16, 16), 256>>>();
    k3_compress<<<dim3(NCHUNK, C_DIM), 224>>>(s, v);
    k4_reduce<<<512, 224>>>();
    k5_globals<<<128, 256>>>(k_wh, k_ws_w, k_ws_b, k_wv, k_wsv_w, k_wsv_b,
                             vp_wh, vp_ws_w, vp_ws_b, vp_wv, vp_wsv_w, vp_wsv_b);
    kb_attn<<<dim3(256, C_DIM), 256, 26496 * 4>>>(out);
}

// round 10
// speedup vs baseline: 1.2488x; 1.2488x over previous
#include <cuda_runtime.h>

#define N_NODES 8192
#define C_DIM   16
#define NC_ITEMS (N_NODES * C_DIM)
#define R_ANCH  32
#define XD      224
#define NCHUNK  64
#define ESCALE  0.15811388300841898f

typedef unsigned long long ull;

__device__ float g_logits[NC_ITEMS * R_ANCH];
__device__ float g_pm[C_DIM * 16 * R_ANCH];
__device__ float g_ps[C_DIM * 16 * R_ANCH];
__device__ float g_part[NCHUNK * C_DIM * R_ANCH * XD];
__device__ float g_gbuf[R_ANCH * C_DIM * XD];
__device__ float g_ke[C_DIM * R_ANCH * XD];
__device__ float g_ve[C_DIM * R_ANCH * XD];
__device__ float g_q[(size_t)NC_ITEMS * XD];

__device__ __forceinline__ float sigf(float x) { return 1.0f / (1.0f + __expf(-x)); }
#define FMA2(d, a, b) asm("fma.rn.f32x2 %0, %1, %2, %0;" : "+l"(d) : "l"(a), "l"(b))
__device__ __forceinline__ ull packx2(float x) {
    ull o; unsigned r = __float_as_uint(x);
    asm("mov.b64 %0, {%1, %1};" : "=l"(o) : "r"(r));
    return o;
}
__device__ __forceinline__ float2 unpk(ull u) {
    float2 f;
    asm("mov.b64 {%0, %1}, %2;" : "=f"(f.x), "=f"(f.y) : "l"(u));
    return f;
}
__device__ __forceinline__ float hadd(ull u) { float2 f = unpk(u); return f.x + f.y; }

// tiny splash kernels so ka lands on the profiled 4th launch (overwritten by k2a)
__global__ void kz(int p) { if (threadIdx.x == 0) g_pm[p] = 0.f; }

// ---- smem layout constants for ka (floats) ----
#define XP   198     // X pitch: cols 0..127 x_s/sig, 128..159 vn_q, 160..191 vn_p
#define WQP  162
#define WPP  162
#define WSVP 134
#define VHP  98
#define OF_WQ   0
#define OF_WP   20736
#define OF_WSV  25920
#define OF_WHQ  30208
#define OF_WHP  31296
#define OF_WVV  32384
#define OF_SBQ  33472
#define OF_SBP  33600
#define OF_SVB  33632
#define OF_X    33664
#define OF_VHS  46336
#define OF_GSB  52608
#define OF_VB   54784
#define KA_SMEM 56448   // floats

// ============================================================
// KA: 64 items/block, 512 threads. k-paired FMA2, zero movs,
// weights used in ORIGINAL k-contiguous layout (no transposes).
// ============================================================
__global__ void __launch_bounds__(512) ka_gvp(
    const float* __restrict__ s, const float* __restrict__ v,
    const float* __restrict__ q_wh, const float* __restrict__ q_ws_w,
    const float* __restrict__ q_ws_b, const float* __restrict__ q_wv,
    const float* __restrict__ q_wsv_w, const float* __restrict__ q_wsv_b,
    const float* __restrict__ wp_wh, const float* __restrict__ wp_ws_w,
    const float* __restrict__ wp_ws_b)
{
    extern __shared__ float sm[];
    float* wq  = sm + OF_WQ;     // [128][162] out-major (k contig)
    float* wp  = sm + OF_WP;     // [32][162]
    float* wsv = sm + OF_WSV;    // [32][134]
    float* whq = sm + OF_WHQ;    // [32][34]
    float* whp = sm + OF_WHP;    // [32][34]
    float* wvv = sm + OF_WVV;    // [32][34]  m-major (h contig)
    float* sbq = sm + OF_SBQ;
    float* sbp = sm + OF_SBP;
    float* svb = sm + OF_SVB;
    float* X   = sm + OF_X;      // [64][198] item-major
    float* vhs = sm + OF_VHS;    // [64][98]
    float* gsb = sm + OF_GSB;    // [64][34]
    float* vbuf= sm + OF_VB;     // [16][104]

    int tid = threadIdx.x, warp = tid >> 5, lane = tid & 31;
    int base = blockIdx.x * 64;

    for (int i = tid; i < 128 * 160; i += 512) { int r = i / 160, c = i - r * 160; wq[r * WQP + c] = q_ws_w[i]; }
    for (int i = tid; i < 32 * 160;  i += 512) { int r = i / 160, c = i - r * 160; wp[r * WPP + c] = wp_ws_w[i]; }
    for (int i = tid; i < 32 * 128;  i += 512) wsv[(i >> 7) * WSVP + (i & 127)] = q_wsv_w[i];
    for (int i = tid; i < 1024;      i += 512) {
        int r = i >> 5, c = i & 31;
        whq[r * 34 + c] = q_wh[i];
        whp[r * 34 + c] = wp_wh[i];
        wvv[r * 34 + c] = q_wv[i];       // [m][h], h contig
    }
    if (tid < 128) sbq[tid] = q_ws_b[tid];
    if (tid < 32)  { sbp[tid] = wp_ws_b[tid]; svb[tid] = q_wsv_b[tid]; }
    __syncthreads();

    // ---- stage A: 16 warps x 4 items; vh/vn via m-paired FMA2 (natural)
    {
        float* vb = vbuf + warp * 104;
        for (int ii = 0; ii < 4; ii++) {
            int i = warp * 4 + ii;
            size_t git = (size_t)(base + i);
            const float* sp = s + git * 128;
            const float* vp = v + git * 96;
            #pragma unroll
            for (int k = 0; k < 4; k++) X[i * XP + lane + 32 * k] = sp[lane + 32 * k];
            #pragma unroll
            for (int k = 0; k < 3; k++) {
                int pos = lane + 32 * k;
                float val = vp[pos];
                int m = pos / 3, d = pos - m * 3;
                vb[d * 34 + m] = val;
            }
            __syncwarp();
            ull aq0 = 0, aq1 = 0, aq2 = 0, ap0 = 0, ap1 = 0, ap2 = 0;
            #pragma unroll
            for (int m2 = 0; m2 < 32; m2 += 2) {
                ull wqp = *(const ull*)&whq[lane * 34 + m2];
                ull wpp = *(const ull*)&whp[lane * 34 + m2];
                ull v0 = *(const ull*)&vb[m2];
                ull v1 = *(const ull*)&vb[34 + m2];
                ull v2 = *(const ull*)&vb[68 + m2];
                FMA2(aq0, v0, wqp); FMA2(aq1, v1, wqp); FMA2(aq2, v2, wqp);
                FMA2(ap0, v0, wpp); FMA2(ap1, v1, wpp); FMA2(ap2, v2, wpp);
            }
            float a0 = hadd(aq0), a1 = hadd(aq1), a2 = hadd(aq2);
            float b0 = hadd(ap0), b1 = hadd(ap1), b2 = hadd(ap2);
            vhs[i * VHP + lane] = a0; vhs[i * VHP + 32 + lane] = a1; vhs[i * VHP + 64 + lane] = a2;
            X[i * XP + 128 + lane] = sqrtf(fmaxf(a0 * a0 + a1 * a1 + a2 * a2, 1e-8f));
            X[i * XP + 160 + lane] = sqrtf(fmaxf(b0 * b0 + b1 * b1 + b2 * b2, 1e-8f));
            __syncwarp();
        }
    }
    __syncthreads();

    float sg[4][8];   // s_out sigmoids held across barrier (warps 0-7)

    if (warp < 8) {
        // ---- s_out: warp 16i x 64o; thread 4i x 8o; k-paired
        int itile = (warp & 3) * 16, otile = (warp >> 2) * 64;
        int ig = lane >> 3, og = lane & 7;
        const float* xb = X + (itile + ig * 4) * XP;
        const float* wb = wq + (otile + og) * WQP;
        ull acc[4][8] = {};
        #pragma unroll 2
        for (int k2 = 0; k2 < 160; k2 += 2) {
            ull xr[4], wr[8];
            #pragma unroll
            for (int e = 0; e < 4; e++) xr[e] = *(const ull*)(xb + e * XP + k2);
            #pragma unroll
            for (int u = 0; u < 8; u++) wr[u] = *(const ull*)(wb + u * 8 * WQP + k2);
            #pragma unroll
            for (int e = 0; e < 4; e++)
                #pragma unroll
                for (int u = 0; u < 8; u++) FMA2(acc[e][u], xr[e], wr[u]);
        }
        #pragma unroll
        for (int e = 0; e < 4; e++) {
            int i = itile + ig * 4 + e;
            size_t g0 = (size_t)(base + i) * 224;
            #pragma unroll
            for (int u = 0; u < 8; u++) {
                int o = otile + og + 8 * u;
                float so = hadd(acc[e][u]) + sbq[o];
                float g = sigf(so);
                sg[e][u] = g;
                g_q[g0 + (o >> 5) * 56 + (o & 31)] = so * g;
            }
        }
    } else {
        // ---- logits: warp tile: i-half x 8 anchors; k-paired
        int w = warp - 8;
        int i = (w & 1) * 32 + lane, ag = w >> 1;
        const float* xb = X + i * XP;
        const float* wb = wp + ag * 8 * WPP;
        ull la[8] = {};
        #pragma unroll 2
        for (int k2 = 0; k2 < 128; k2 += 2) {
            ull xp = *(const ull*)(xb + k2);
            #pragma unroll
            for (int aa = 0; aa < 8; aa++)
                FMA2(la[aa], xp, *(const ull*)(wb + aa * WPP + k2));
        }
        #pragma unroll 2
        for (int t = 0; t < 32; t += 2) {
            ull xp = *(const ull*)(xb + 160 + t);
            #pragma unroll
            for (int aa = 0; aa < 8; aa++)
                FMA2(la[aa], xp, *(const ull*)(wb + aa * WPP + 128 + t));
        }
        size_t gl = (size_t)(base + i) * 32 + ag * 8;
        #pragma unroll
        for (int aa = 0; aa < 8; aa++)
            g_logits[gl + aa] = hadd(la[aa]) + sbp[ag * 8 + aa];
    }
    __syncthreads();   // all X readers (logits) done

    if (warp < 8) {
        // sig -> X cols 0..127
        int itile = (warp & 3) * 16, otile = (warp >> 2) * 64;
        int ig = lane >> 3, og = lane & 7;
        #pragma unroll
        for (int e = 0; e < 4; e++) {
            int i = itile + ig * 4 + e;
            #pragma unroll
            for (int u = 0; u < 8; u++)
                X[i * XP + otile + og + 8 * u] = sg[e][u];
        }
    }
    __syncthreads();   // sig visible

    if (warp < 8) {
        // ---- gate: thread = 1i x 8m; o-paired (wsv natural [m][o])
        int i = (warp & 1) * 32 + lane, mg = warp >> 1;
        const float* xb = X + i * XP;
        const float* wb = wsv + mg * 8 * WSVP;
        ull ga[8] = {};
        #pragma unroll 2
        for (int o2 = 0; o2 < 128; o2 += 2) {
            ull sp = *(const ull*)(xb + o2);
            #pragma unroll
            for (int mm = 0; mm < 8; mm++)
                FMA2(ga[mm], sp, *(const ull*)(wb + mm * WSVP + o2));
        }
        #pragma unroll
        for (int mm = 0; mm < 8; mm++) {
            int m = mg * 8 + mm;
            gsb[i * 34 + m] = sigf(hadd(ga[mm]) + svb[m]);
        }
    }
    __syncthreads();   // gsb visible

    // ---- v_out: all 512 threads; thread = 1i x 4m x 3d; h-paired
    {
        int i = tid >> 3, g = tid & 7;
        const float* vr = vhs + i * VHP;
        ull av[4][3] = {};
        #pragma unroll 2
        for (int h2 = 0; h2 < 32; h2 += 2) {
            ull v0 = *(const ull*)(vr + h2);
            ull v1 = *(const ull*)(vr + 32 + h2);
            ull v2 = *(const ull*)(vr + 64 + h2);
            #pragma unroll
            for (int u = 0; u < 4; u++) {
                ull wr = *(const ull*)(wvv + (g + 8 * u) * 34 + h2);
                FMA2(av[u][0], v0, wr);
                FMA2(av[u][1], v1, wr);
                FMA2(av[u][2], v2, wr);
            }
        }
        size_t g0 = (size_t)(base + i) * 224;
        #pragma unroll
        for (int u = 0; u < 4; u++) {
            int m = g + 8 * u;
            float gv = gsb[i * 34 + m];
            int gpos = (m >> 3) * 56 + 32 + (m & 7) * 3;
            #pragma unroll
            for (int d = 0; d < 3; d++)
                g_q[g0 + gpos + d] = hadd(av[u][d]) * gv;
        }
    }
}

// ---- K2a: per-(c,seg) partial online softmax stats ----
__global__ void __launch_bounds__(256) k2a_stats() {
    __shared__ float redm[8 * 33], reds[8 * 33];
    int seg = blockIdx.x, c = blockIdx.y;
    int t = threadIdx.x, a = t & 31, part = t >> 5;
    float m = -3.4e38f, sum = 0.f;
    int nb = seg * 512 + part * 64;
    for (int i = 0; i < 64; i++) {
        float val = g_logits[((size_t)(nb + i) * C_DIM + c) * 32 + a];
        float nm = fmaxf(m, val);
        sum = sum * __expf(m - nm) + __expf(val - nm);
        m = nm;
    }
    redm[part * 33 + a] = m; reds[part * 33 + a] = sum;
    __syncthreads();
    if (t < 32) {
        float mm = redm[t], ss = reds[t];
        #pragma unroll
        for (int p = 1; p < 8; p++) {
            float m2 = redm[p * 33 + t], s2 = reds[p * 33 + t];
            float nm = fmaxf(mm, m2);
            ss = ss * __expf(mm - nm) + s2 * __expf(m2 - nm);
            mm = nm;
        }
        g_pm[(c * 16 + seg) * 32 + t] = mm;
        g_ps[(c * 16 + seg) * 32 + t] = ss;
    }
}

// ---- K3: compress partials (merges softmax stats inline) ----
__global__ void __launch_bounds__(224) k3_compress(const float* __restrict__ s,
                                                   const float* __restrict__ v) {
    __shared__ float xt[32 * 226];
    __shared__ float wt[32 * 33];
    __shared__ float mloc[32], iloc[32];
    int t = threadIdx.x;
    int chunk = blockIdx.x, c = blockIdx.y;
    if (t < 32) {
        float m = -3.4e38f;
        #pragma unroll
        for (int sg2 = 0; sg2 < 16; sg2++) m = fmaxf(m, g_pm[(c * 16 + sg2) * 32 + t]);
        float sum = 0.f;
        #pragma unroll
        for (int sg2 = 0; sg2 < 16; sg2++)
            sum += g_ps[(c * 16 + sg2) * 32 + t] * __expf(g_pm[(c * 16 + sg2) * 32 + t] - m);
        mloc[t] = m; iloc[t] = 1.0f / sum;
    }
    int a0 = (t & 7) * 4, j0 = (t >> 3) * 8;
    ull acc[4][4] = {};
    for (int sub = 0; sub < 4; sub++) {
        __syncthreads();
        #pragma unroll 4
        for (int n = 0; n < 32; n++) {
            int item = (chunk * 128 + sub * 32 + n) * C_DIM + c;
            xt[n * 226 + t] = (t < 128) ? s[(size_t)item * 128 + t]
                                        : v[(size_t)item * 96 + (t - 128)];
        }
        for (int idx = t; idx < 1024; idx += 224) {
            int n = idx >> 5, a = idx & 31;
            int item = (chunk * 128 + sub * 32 + n) * C_DIM + c;
            wt[n * 33 + a] = __expf(g_logits[(size_t)item * 32 + a] - mloc[a]) * iloc[a];
        }
        __syncthreads();
        #pragma unroll 4
        for (int n = 0; n < 32; n++) {
            ull wpk[4];
            #pragma unroll
            for (int u = 0; u < 4; u++) wpk[u] = packx2(wt[n * 33 + a0 + u]);
            const ull* x2 = (const ull*)(xt + n * 226 + j0);
            #pragma unroll
            for (int vv = 0; vv < 4; vv++) {
                ull xp = x2[vv];
                FMA2(acc[0][vv], wpk[0], xp);
                FMA2(acc[1][vv], wpk[1], xp);
                FMA2(acc[2][vv], wpk[2], xp);
                FMA2(acc[3][vv], wpk[3], xp);
            }
        }
    }
    #pragma unroll
    for (int u = 0; u < 4; u++) {
        size_t basep = ((size_t)(chunk * C_DIM + c) * 32 + a0 + u) * 224 + j0;
        #pragma unroll
        for (int vv = 0; vv < 4; vv++) {
            float2 fr = unpk(acc[u][vv]);
            *(float2*)&g_part[basep + 2 * vv] = fr;
        }
    }
}

// ---- K4 ----
__global__ void k4_reduce() {
    int bx = blockIdx.x; int c = bx >> 5, a = bx & 31; int t = threadIdx.x;
    float sum = 0.f;
    for (int ch = 0; ch < NCHUNK; ++ch)
        sum += g_part[((size_t)(ch * C_DIM + c) * 32 + a) * 224 + t];
    g_gbuf[(a * C_DIM + c) * 224 + t] = sum;
}

// ---- K5 ----
__global__ void k5_globals(
    const float* __restrict__ k_wh, const float* __restrict__ k_ws_w, const float* __restrict__ k_ws_b,
    const float* __restrict__ k_wv, const float* __restrict__ k_wsv_w, const float* __restrict__ k_wsv_b,
    const float* __restrict__ p_wh, const float* __restrict__ p_ws_w, const float* __restrict__ p_ws_b,
    const float* __restrict__ p_wv, const float* __restrict__ p_wsv_w, const float* __restrict__ p_wsv_b) {
    __shared__ float wx[8][608];
    int tid = threadIdx.x, warp = tid >> 5, lane = tid & 31;
    int w = blockIdx.x * 8 + warp;
    int which = w >> 9, item = w & 511;
    const float* wh   = which ? p_wh    : k_wh;
    const float* wsw  = which ? p_ws_w  : k_ws_w;
    const float* wsb  = which ? p_ws_b  : k_ws_b;
    const float* wv   = which ? p_wv    : k_wv;
    const float* wsvw = which ? p_wsv_w : k_wsv_w;
    const float* wsvb = which ? p_wsv_b : k_wsv_b;
    float* x = wx[warp]; float* vhsl = x + 224; float* vns = x + 320; float* sig = x + 480;
    const float* gp = &g_gbuf[item * 224];
    #pragma unroll
    for (int k = 0; k < 7; k++) x[lane + 32 * k] = gp[lane + 32 * k];
    __syncwarp();
    float a0 = 0.f, a1 = 0.f, a2 = 0.f;
    #pragma unroll
    for (int i = 0; i < 32; i++) {
        float ww = __ldg(&wh[lane * 32 + i]);
        a0 = fmaf(x[128 + i * 3 + 0], ww, a0);
        a1 = fmaf(x[128 + i * 3 + 1], ww, a1);
        a2 = fmaf(x[128 + i * 3 + 2], ww, a2);
    }
    vhsl[lane] = a0; vhsl[32 + lane] = a1; vhsl[64 + lane] = a2;
    vns[lane] = sqrtf(fmaxf(a0 * a0 + a1 * a1 + a2 * a2, 1e-8f));
    __syncwarp();
    float so[4];
    #pragma unroll
    for (int k = 0; k < 4; k++) {
        int o = lane + 32 * k;
        float acc = __ldg(&wsb[o]);
        const float* wr = &wsw[o * 160];
        #pragma unroll
        for (int j = 0; j < 128; j++) acc = fmaf(x[j], __ldg(&wr[j]), acc);
        #pragma unroll
        for (int j = 0; j < 32; j++) acc = fmaf(vns[j], __ldg(&wr[128 + j]), acc);
        so[k] = acc;
        sig[o] = sigf(acc);
    }
    __syncwarp();
    float g = __ldg(&wsvb[lane]);
    #pragma unroll
    for (int j = 0; j < 128; j++) g = fmaf(sig[j], __ldg(&wsvw[lane * 128 + j]), g);
    float gs = sigf(g);
    float* outp = which ? g_ve : g_ke;
    int a = item >> 4, cc = item & 15;
    size_t ob = ((size_t)cc * 32 + a) * 224;
    int h = lane >> 3;
    int vpos = h * 56 + 32 + (lane & 7) * 3;
    #pragma unroll
    for (int d = 0; d < 3; d++) {
        float vo = 0.f;
        #pragma unroll
        for (int hh = 0; hh < 32; hh++) vo = fmaf(vhsl[d * 32 + hh], __ldg(&wv[lane * 32 + hh]), vo);
        outp[ob + vpos + d] = vo * gs;
    }
    #pragma unroll
    for (int k = 0; k < 4; k++) { int o = lane + 32 * k; outp[ob + k * 56 + lane] = so[k] * sig[o]; }
}

// ---- KB: attention, 32 items x 1 channel, 256 threads ----
__global__ void __launch_bounds__(256) kb_attn(float* __restrict__ out) {
    extern __shared__ float sm[];
    float* qe  = sm;            // [224][33]
    float* keT = sm + 7392;     // [224][34]
    float* ve  = sm + 15008;    // [32][226]
    float* al  = sm + 22240;    // [32][133]
    int tid = threadIdx.x;
    int c = blockIdx.y;
    int nb = blockIdx.x * 32;

    for (int idx = tid; idx < 32 * 224; idx += 256) {
        int i = idx / 224, pos = idx - i * 224;
        size_t git = (size_t)(nb + i) * 16 + c;
        qe[pos * 33 + i] = g_q[git * 224 + pos];
    }
    for (int idx = tid; idx < 32 * 224; idx += 256) {
        int r = idx / 224, pos = idx - r * 224;
        size_t gb = ((size_t)c * 32 + r) * 224 + pos;
        keT[pos * 34 + r] = g_ke[gb];
        ve[r * 226 + pos] = g_ve[gb];
    }
    __syncthreads();

    int h = tid >> 6, rem = tid & 63;

    {
        int ig = rem >> 3, rg = rem & 7;
        ull acc[4][2] = {};
        #pragma unroll 2
        for (int k = 0; k < 56; k++) {
            int row = h * 56 + k;
            ull qp[4];
            #pragma unroll
            for (int e = 0; e < 4; e++) qp[e] = packx2(qe[row * 33 + ig * 4 + e]);
            const ull* k2 = (const ull*)(keT + row * 34 + rg * 4);
            #pragma unroll
            for (int u = 0; u < 2; u++) {
                ull kp = k2[u];
                FMA2(acc[0][u], qp[0], kp);
                FMA2(acc[1][u], qp[1], kp);
                FMA2(acc[2][u], qp[2], kp);
                FMA2(acc[3][u], qp[3], kp);
            }
        }
        #pragma unroll
        for (int e = 0; e < 4; e++)
            #pragma unroll
            for (int u = 0; u < 2; u++) {
                float2 fr = unpk(acc[e][u]);
                al[(ig * 4 + e) * 133 + h * 33 + rg * 4 + 2 * u]     = fr.x * ESCALE;
                al[(ig * 4 + e) * 133 + h * 33 + rg * 4 + 2 * u + 1] = fr.y * ESCALE;
            }
    }
    __syncthreads();

    if (tid < 128) {
        int i = tid >> 2, h2 = tid & 3;
        float* row = &al[i * 133 + h2 * 33];
        float ev[32], mx = -3.4e38f;
        #pragma unroll
        for (int k = 0; k < 32; k++) { ev[k] = row[k]; mx = fmaxf(mx, ev[k]); }
        float sum = 0.f;
        #pragma unroll
        for (int k = 0; k < 32; k++) { ev[k] = __expf(ev[k] - mx); sum += ev[k]; }
        float inv = 1.0f / sum;
        #pragma unroll
        for (int k = 0; k < 32; k++) row[k] = ev[k] * inv;
    }
    __syncthreads();

    {
        int ig = rem >> 2, j = rem & 3;
        ull accs[2][4] = {};
        ull accv[2][3] = {};
        #pragma unroll 2
        for (int r = 0; r < 32; r++) {
            ull ap[2];
            #pragma unroll
            for (int e = 0; e < 2; e++) ap[e] = packx2(al[(ig * 2 + e) * 133 + h * 33 + r]);
            const ull* vs2 = (const ull*)(ve + r * 226 + h * 56 + j * 8);
            const ull* vv2 = (const ull*)(ve + r * 226 + h * 56 + 32 + j * 6);
            #pragma unroll
            for (int u = 0; u < 4; u++) {
                ull vp = vs2[u];
                FMA2(accs[0][u], ap[0], vp);
                FMA2(accs[1][u], ap[1], vp);
            }
            #pragma unroll
            for (int u = 0; u < 3; u++) {
                ull vp = vv2[u];
                FMA2(accv[0][u], ap[0], vp);
                FMA2(accv[1][u], ap[1], vp);
            }
        }
        #pragma unroll
        for (int e = 0; e < 2; e++) {
            size_t git = (size_t)(nb + ig * 2 + e) * 16 + c;
            float* ds = &out[git * 128 + h * 32 + j * 8];
            #pragma unroll
            for (int u = 0; u < 4; u++) *(float2*)&ds[2 * u] = unpk(accs[e][u]);
            float* dv = &out[(size_t)NC_ITEMS * 128 + git * 96 + h * 24 + j * 6];
            #pragma unroll
            for (int u = 0; u < 3; u++) *(float2*)&dv[2 * u] = unpk(accv[e][u]);
        }
    }
}

// ============================================================
extern "C" void kernel_launch(void* const* d_in, const int* in_sizes, int n_in,
                              void* d_out, int out_size) {
    (void)in_sizes; (void)n_in; (void)out_size;
    const float* s       = (const float*)d_in[0];
    const float* v       = (const float*)d_in[1];
    const float* wp_wh   = (const float*)d_in[2];
    const float* wp_ws_w = (const float*)d_in[3];
    const float* wp_ws_b = (const float*)d_in[4];
    const float* q_wh    = (const float*)d_in[5];
    const float* q_ws_w  = (const float*)d_in[6];
    const float* q_ws_b  = (const float*)d_in[7];
    const float* q_wv    = (const float*)d_in[8];
    const float* q_wsv_w = (const float*)d_in[9];
    const float* q_wsv_b = (const float*)d_in[10];
    const float* k_wh    = (const float*)d_in[11];
    const float* k_ws_w  = (const float*)d_in[12];
    const float* k_ws_b  = (const float*)d_in[13];
    const float* k_wv    = (const float*)d_in[14];
    const float* k_wsv_w = (const float*)d_in[15];
    const float* k_wsv_b = (const float*)d_in[16];
    const float* vp_wh   = (const float*)d_in[17];
    const float* vp_ws_w = (const float*)d_in[18];
    const float* vp_ws_b = (const float*)d_in[19];
    const float* vp_wv   = (const float*)d_in[20];
    const float* vp_wsv_w= (const float*)d_in[21];
    const float* vp_wsv_b= (const float*)d_in[22];
    float* out = (float*)d_out;

    cudaFuncSetAttribute((const void*)ka_gvp,  cudaFuncAttributeMaxDynamicSharedMemorySize, KA_SMEM * 4);
    cudaFuncSetAttribute((const void*)kb_attn, cudaFuncAttributeMaxDynamicSharedMemorySize, 26496 * 4);

    kz<<<1, 32>>>(0);
    kz<<<1, 32>>>(1);
    kz<<<1, 32>>>(2);
    ka_gvp<<<2048, 512, KA_SMEM * 4>>>(s, v, q_wh, q_ws_w, q_ws_b, q_wv,
                                       q_wsv_w, q_wsv_b, wp_wh, wp_ws_w, wp_ws_b);  // 4th -> profiled
    k2a_stats<<<dim3(16, 16), 256>>>();
    k3_compress<<<dim3(NCHUNK, C_DIM), 224>>>(s, v);
    k4_reduce<<<512, 224>>>();
    k5_globals<<<128, 256>>>(k_wh, k_ws_w, k_ws_b, k_wv, k_wsv_w, k_wsv_b,
                             vp_wh, vp_ws_w, vp_ws_b, vp_wv, vp_wsv_w, vp_wsv_b);
    kb_attn<<<dim3(256, C_DIM), 256, 26496 * 4>>>(out);
}